// round 1
// baseline (speedup 1.0000x reference)
#include <cuda_runtime.h>
#include <float.h>
#include <math.h>

// Problem constants (fixed by reference setup_inputs)
#define BB 8
#define SS 4096
#define CC 1024
#define HH 64
#define NS 16           // S splits for partial reduction
#define SROWS (SS/NS)   // 256 rows per partial block

// Scratch (no allocations allowed in kernel_launch)
__device__ float g_psum[BB*NS*CC];
__device__ float g_pmax[BB*NS*CC];
__device__ float g_mean[BB*CC];
__device__ float g_max [BB*CC];
__device__ float g_a   [BB*CC];

// ---------------------------------------------------------------------------
// Kernel 1: partial masked sum/max over a 256-row chunk, 256 channels/block.
// Skips entire rows where mask==0 (saves ~50% of the 128MB read).
// ---------------------------------------------------------------------------
__global__ void k_partial(const float* __restrict__ x,
                          const int*   __restrict__ mask) {
    const int b  = blockIdx.z;
    const int ns = blockIdx.y;
    const int c  = blockIdx.x * blockDim.x + threadIdx.x;   // 0..1023

    __shared__ int smask[SROWS];
    const int s0 = ns * SROWS;
    for (int i = threadIdx.x; i < SROWS; i += blockDim.x)
        smask[i] = mask[b * SS + s0 + i];
    __syncthreads();

    float sum = 0.0f;
    float mx  = -FLT_MAX;
    const float* xp = x + ((size_t)b * SS + s0) * CC + c;
    #pragma unroll 4
    for (int i = 0; i < SROWS; i++) {
        if (smask[i]) {
            float v = xp[(size_t)i * CC];
            sum += v;
            mx = fmaxf(mx, v);
        }
    }
    g_psum[(b * NS + ns) * CC + c] = sum;
    g_pmax[(b * NS + ns) * CC + c] = mx;
}

// ---------------------------------------------------------------------------
// Kernel 2: fold NS partials -> mean/max; compute count[b] from mask.
// Grid (C/256, B), 256 threads.
// ---------------------------------------------------------------------------
__global__ void k_finalize(const int* __restrict__ mask) {
    const int b = blockIdx.y;
    const int c = blockIdx.x * blockDim.x + threadIdx.x;

    // Per-block redundant count reduction (trivial: 4096 ints)
    __shared__ int sred[256];
    int cnt = 0;
    for (int i = threadIdx.x; i < SS; i += blockDim.x)
        cnt += mask[b * SS + i];
    sred[threadIdx.x] = cnt;
    __syncthreads();
    for (int off = 128; off > 0; off >>= 1) {
        if (threadIdx.x < off) sred[threadIdx.x] += sred[threadIdx.x + off];
        __syncthreads();
    }
    const float count = fmaxf((float)sred[0], 1.0f);

    float sum = 0.0f;
    float mx  = -FLT_MAX;
    #pragma unroll
    for (int ns = 0; ns < NS; ns++) {
        sum += g_psum[(b * NS + ns) * CC + c];
        mx = fmaxf(mx, g_pmax[(b * NS + ns) * CC + c]);
    }
    g_mean[b * CC + c] = sum / count;
    g_max [b * CC + c] = mx;
}

// ---------------------------------------------------------------------------
// Kernel 3: a = sigmoid(mlp(mean) + mlp(max))
//          = sigmoid((relu(mean@W0^T) + relu(max@W0^T)) @ W1^T)
// One block per batch row, 256 threads (8 warps).
// ---------------------------------------------------------------------------
__global__ void k_mlp(const float* __restrict__ W0,   // [H, C]
                      const float* __restrict__ W1) { // [C, H]
    const int b = blockIdx.x;
    __shared__ float smean[CC];
    __shared__ float smax [CC];
    __shared__ float hsum [HH];

    for (int i = threadIdx.x; i < CC; i += blockDim.x) {
        smean[i] = g_mean[b * CC + i];
        smax [i] = g_max [b * CC + i];
    }
    __syncthreads();

    const int warp = threadIdx.x >> 5;
    const int lane = threadIdx.x & 31;

    // 8 warps x 8 hidden units each
    for (int j = warp; j < HH; j += 8) {
        const float* w = W0 + j * CC;
        float dm = 0.0f, dx = 0.0f;
        for (int k = lane; k < CC; k += 32) {
            float wv = w[k];
            dm += wv * smean[k];
            dx += wv * smax[k];
        }
        #pragma unroll
        for (int off = 16; off > 0; off >>= 1) {
            dm += __shfl_xor_sync(0xFFFFFFFFu, dm, off);
            dx += __shfl_xor_sync(0xFFFFFFFFu, dx, off);
        }
        if (lane == 0)
            hsum[j] = fmaxf(dm, 0.0f) + fmaxf(dx, 0.0f);
    }
    __syncthreads();

    for (int c = threadIdx.x; c < CC; c += blockDim.x) {
        const float* w1 = W1 + c * HH;
        float acc = 0.0f;
        #pragma unroll
        for (int j = 0; j < HH; j++)
            acc += w1[j] * hsum[j];
        g_a[b * CC + c] = 1.0f / (1.0f + expf(-acc));
    }
}

// ---------------------------------------------------------------------------
// Kernel 4: out[b,s,c] = x[b,s,c] * a[b,c]   (float4 streaming)
// ---------------------------------------------------------------------------
__global__ void k_scale(const float* __restrict__ x,
                        float*       __restrict__ out) {
    const size_t i = (size_t)blockIdx.x * blockDim.x + threadIdx.x; // float4 idx
    const size_t total4 = (size_t)BB * SS * CC / 4;
    if (i >= total4) return;

    const size_t e = i * 4;                      // element index
    const int b = (int)(e / ((size_t)SS * CC));
    const int c = (int)(e % CC);                 // multiple of 4

    float4 v = reinterpret_cast<const float4*>(x)[i];
    float4 a = *reinterpret_cast<const float4*>(&g_a[b * CC + c]);
    v.x *= a.x; v.y *= a.y; v.z *= a.z; v.w *= a.w;
    reinterpret_cast<float4*>(out)[i] = v;
}

// ---------------------------------------------------------------------------
extern "C" void kernel_launch(void* const* d_in, const int* in_sizes, int n_in,
                              void* d_out, int out_size) {
    const float* x    = (const float*)d_in[0];   // [B,S,C]
    const int*   mask = (const int*)  d_in[1];   // [B,S]
    const float* W0   = (const float*)d_in[2];   // [H,C]
    const float* W1   = (const float*)d_in[3];   // [C,H]
    float*       out  = (float*)d_out;           // [B,S,C]

    (void)in_sizes; (void)n_in; (void)out_size;

    {   // partial reduction
        dim3 grid(CC / 256, NS, BB);
        k_partial<<<grid, 256>>>(x, mask);
    }
    {   // finalize mean/max
        dim3 grid(CC / 256, BB);
        k_finalize<<<grid, 256>>>(mask);
    }
    {   // MLP + sigmoid
        k_mlp<<<BB, 256>>>(W0, W1);
    }
    {   // scale
        const size_t total4 = (size_t)BB * SS * CC / 4;   // 8,388,608
        const int threads = 256;
        const int blocks = (int)((total4 + threads - 1) / threads);
        k_scale<<<blocks, threads>>>(x, out);
    }
}

// round 2
// speedup vs baseline: 1.2039x; 1.2039x over previous
#include <cuda_runtime.h>
#include <float.h>
#include <math.h>

// Problem constants (fixed by reference setup_inputs)
#define BB 8
#define SS 4096
#define CC 1024
#define HH 64
#define NS 64           // S splits for partial reduction
#define SROWS (SS/NS)   // 64 rows per partial block

// Scratch (no allocations allowed in kernel_launch)
__device__ float g_psum[BB*NS*CC];
__device__ float g_pmax[BB*NS*CC];
__device__ float g_mean[BB*CC];
__device__ float g_max [BB*CC];
__device__ float g_a   [BB*CC];

// ---------------------------------------------------------------------------
// Kernel 1: partial masked sum/max over a 64-row chunk, full 1024 channels.
// float4 per thread (4 channels). Rows with mask==0 are skipped entirely,
// so their cache lines are never requested from HBM.
// grid (NS, BB), 256 threads.
// ---------------------------------------------------------------------------
__global__ void k_partial(const float* __restrict__ x,
                          const int*   __restrict__ mask) {
    const int ns = blockIdx.x;
    const int b  = blockIdx.y;
    const int c4 = threadIdx.x;              // float4 index 0..255

    __shared__ int smask[SROWS];
    const int s0 = ns * SROWS;
    if (threadIdx.x < SROWS)
        smask[threadIdx.x] = mask[b * SS + s0 + threadIdx.x];
    __syncthreads();

    float4 sum = make_float4(0.f, 0.f, 0.f, 0.f);
    float4 mx  = make_float4(-FLT_MAX, -FLT_MAX, -FLT_MAX, -FLT_MAX);

    const float4* xp = reinterpret_cast<const float4*>(
        x + ((size_t)b * SS + s0) * CC) + c4;

    #pragma unroll 8
    for (int i = 0; i < SROWS; i++) {
        if (smask[i]) {
            float4 v = xp[(size_t)i * (CC / 4)];
            sum.x += v.x; sum.y += v.y; sum.z += v.z; sum.w += v.w;
            mx.x = fmaxf(mx.x, v.x); mx.y = fmaxf(mx.y, v.y);
            mx.z = fmaxf(mx.z, v.z); mx.w = fmaxf(mx.w, v.w);
        }
    }

    float4* ps = reinterpret_cast<float4*>(g_psum + (b * NS + ns) * CC);
    float4* pm = reinterpret_cast<float4*>(g_pmax + (b * NS + ns) * CC);
    ps[c4] = sum;
    pm[c4] = mx;
}

// ---------------------------------------------------------------------------
// Kernel 2: fold NS partials -> mean/max; compute count[b] from mask.
// grid (CC/256, BB), 256 threads.
// ---------------------------------------------------------------------------
__global__ void k_finalize(const int* __restrict__ mask) {
    const int b = blockIdx.y;
    const int c = blockIdx.x * blockDim.x + threadIdx.x;

    __shared__ int sred[256];
    int cnt = 0;
    for (int i = threadIdx.x; i < SS; i += blockDim.x)
        cnt += mask[b * SS + i];
    sred[threadIdx.x] = cnt;
    __syncthreads();
    for (int off = 128; off > 0; off >>= 1) {
        if (threadIdx.x < off) sred[threadIdx.x] += sred[threadIdx.x + off];
        __syncthreads();
    }
    const float count = fmaxf((float)sred[0], 1.0f);

    float sum = 0.0f;
    float mx  = -FLT_MAX;
    #pragma unroll
    for (int ns = 0; ns < NS; ns++) {
        sum += g_psum[(b * NS + ns) * CC + c];
        mx = fmaxf(mx, g_pmax[(b * NS + ns) * CC + c]);
    }
    g_mean[b * CC + c] = sum / count;
    g_max [b * CC + c] = mx;
}

// ---------------------------------------------------------------------------
// Kernel 3: a = sigmoid(mlp(mean) + mlp(max))
//          = sigmoid((relu(mean@W0^T) + relu(max@W0^T)) @ W1^T)
// One block per batch row, 256 threads (8 warps).
// ---------------------------------------------------------------------------
__global__ void k_mlp(const float* __restrict__ W0,   // [H, C]
                      const float* __restrict__ W1) { // [C, H]
    const int b = blockIdx.x;
    __shared__ float smean[CC];
    __shared__ float smax [CC];
    __shared__ float hsum [HH];

    for (int i = threadIdx.x; i < CC; i += blockDim.x) {
        smean[i] = g_mean[b * CC + i];
        smax [i] = g_max [b * CC + i];
    }
    __syncthreads();

    const int warp = threadIdx.x >> 5;
    const int lane = threadIdx.x & 31;

    for (int j = warp; j < HH; j += 8) {
        const float* w = W0 + j * CC;
        float dm = 0.0f, dx = 0.0f;
        for (int k = lane; k < CC; k += 32) {
            float wv = w[k];
            dm += wv * smean[k];
            dx += wv * smax[k];
        }
        #pragma unroll
        for (int off = 16; off > 0; off >>= 1) {
            dm += __shfl_xor_sync(0xFFFFFFFFu, dm, off);
            dx += __shfl_xor_sync(0xFFFFFFFFu, dx, off);
        }
        if (lane == 0)
            hsum[j] = fmaxf(dm, 0.0f) + fmaxf(dx, 0.0f);
    }
    __syncthreads();

    for (int c = threadIdx.x; c < CC; c += blockDim.x) {
        const float* w1 = W1 + c * HH;
        float acc = 0.0f;
        #pragma unroll
        for (int j = 0; j < HH; j++)
            acc += w1[j] * hsum[j];
        g_a[b * CC + c] = 1.0f / (1.0f + expf(-acc));
    }
}

// ---------------------------------------------------------------------------
// Kernel 4: out[b,s,c] = x[b,s,c] * a[b,c]   (float4 streaming)
// grid ((S*C/4)/256, B) -> batch from blockIdx.y, no 64-bit division.
// ---------------------------------------------------------------------------
__global__ void k_scale(const float* __restrict__ x,
                        float*       __restrict__ out) {
    const int b = blockIdx.y;
    const unsigned i = blockIdx.x * blockDim.x + threadIdx.x;  // float4 idx in batch
    const unsigned c4 = i & (CC / 4 - 1);                       // 0..255

    const size_t gi = (size_t)b * (SS * CC / 4) + i;
    float4 v = reinterpret_cast<const float4*>(x)[gi];
    float4 a = reinterpret_cast<const float4*>(g_a + b * CC)[c4];
    v.x *= a.x; v.y *= a.y; v.z *= a.z; v.w *= a.w;
    reinterpret_cast<float4*>(out)[gi] = v;
}

// ---------------------------------------------------------------------------
extern "C" void kernel_launch(void* const* d_in, const int* in_sizes, int n_in,
                              void* d_out, int out_size) {
    const float* x    = (const float*)d_in[0];   // [B,S,C]
    const int*   mask = (const int*)  d_in[1];   // [B,S]
    const float* W0   = (const float*)d_in[2];   // [H,C]
    const float* W1   = (const float*)d_in[3];   // [C,H]
    float*       out  = (float*)d_out;           // [B,S,C]

    (void)in_sizes; (void)n_in; (void)out_size;

    {   // partial reduction
        dim3 grid(NS, BB);
        k_partial<<<grid, 256>>>(x, mask);
    }
    {   // finalize mean/max
        dim3 grid(CC / 256, BB);
        k_finalize<<<grid, 256>>>(mask);
    }
    {   // MLP + sigmoid
        k_mlp<<<BB, 256>>>(W0, W1);
    }
    {   // scale
        dim3 grid((SS * CC / 4) / 256, BB);     // (4096, 8)
        k_scale<<<grid, 256>>>(x, out);
    }
}

// round 3
// speedup vs baseline: 2.0019x; 1.6629x over previous
#include <cuda_runtime.h>
#include <float.h>
#include <math.h>

// Problem constants (fixed by reference setup_inputs)
#define BB 8
#define SS 4096
#define CC 1024
#define HH 64
#define NS 64           // S splits for partial reduction
#define SROWS (SS/NS)   // 64 rows per partial chunk

// Scratch (no allocations allowed in kernel_launch)
__device__ float g_psum[BB*NS*CC];
__device__ float g_pmax[BB*NS*CC];
__device__ int   g_pcnt[BB*NS];
__device__ float g_mean[BB*CC];
__device__ float g_max [BB*CC];
__device__ float g_hsum[BB*HH];
__device__ float g_a   [BB*CC];

// ---------------------------------------------------------------------------
// Kernel 1: partial masked sum/max over a 64-row chunk, full 1024 channels.
// Valid rows are compacted into a smem list first -> branch-free inner loop,
// 2 rows per iteration for load-level parallelism. grid (NS, BB), 256 thr.
// ---------------------------------------------------------------------------
__global__ void k_partial(const float* __restrict__ x,
                          const int*   __restrict__ mask) {
    const int ns = blockIdx.x;
    const int b  = blockIdx.y;
    const int c4 = threadIdx.x;              // float4 index 0..255

    __shared__ int smask[SROWS];
    __shared__ int srows[SROWS];
    __shared__ int snv;
    const int s0 = ns * SROWS;
    if (threadIdx.x < SROWS)
        smask[threadIdx.x] = mask[b * SS + s0 + threadIdx.x];
    __syncthreads();
    if (threadIdx.x == 0) {
        int nv = 0;
        #pragma unroll
        for (int i = 0; i < SROWS; i++)
            if (smask[i]) srows[nv++] = i;
        snv = nv;
        g_pcnt[b * NS + ns] = nv;
    }
    __syncthreads();
    const int nv = snv;

    float4 sum = make_float4(0.f, 0.f, 0.f, 0.f);
    float4 mx  = make_float4(-FLT_MAX, -FLT_MAX, -FLT_MAX, -FLT_MAX);

    const float4* xp = reinterpret_cast<const float4*>(
        x + ((size_t)b * SS + s0) * CC) + c4;

    int i = 0;
    #pragma unroll 2
    for (; i + 2 <= nv; i += 2) {
        const int r0 = srows[i];
        const int r1 = srows[i + 1];
        float4 v0 = xp[(size_t)r0 * (CC / 4)];
        float4 v1 = xp[(size_t)r1 * (CC / 4)];
        sum.x += v0.x; sum.y += v0.y; sum.z += v0.z; sum.w += v0.w;
        mx.x = fmaxf(mx.x, v0.x); mx.y = fmaxf(mx.y, v0.y);
        mx.z = fmaxf(mx.z, v0.z); mx.w = fmaxf(mx.w, v0.w);
        sum.x += v1.x; sum.y += v1.y; sum.z += v1.z; sum.w += v1.w;
        mx.x = fmaxf(mx.x, v1.x); mx.y = fmaxf(mx.y, v1.y);
        mx.z = fmaxf(mx.z, v1.z); mx.w = fmaxf(mx.w, v1.w);
    }
    if (i < nv) {
        const int r0 = srows[i];
        float4 v0 = xp[(size_t)r0 * (CC / 4)];
        sum.x += v0.x; sum.y += v0.y; sum.z += v0.z; sum.w += v0.w;
        mx.x = fmaxf(mx.x, v0.x); mx.y = fmaxf(mx.y, v0.y);
        mx.z = fmaxf(mx.z, v0.z); mx.w = fmaxf(mx.w, v0.w);
    }

    reinterpret_cast<float4*>(g_psum + (b * NS + ns) * CC)[c4] = sum;
    reinterpret_cast<float4*>(g_pmax + (b * NS + ns) * CC)[c4] = mx;
}

// ---------------------------------------------------------------------------
// Kernel 2: fold NS partials -> mean/max. grid (CC/4/32 = 8, BB), 256 thr.
// Thread (g = tx&31, sl = tx>>5): channel-group g, ns slice sl (8 partials).
// ---------------------------------------------------------------------------
__global__ void k_finalize() {
    const int b  = blockIdx.y;
    const int g  = threadIdx.x & 31;         // 0..31 channel group in block
    const int sl = threadIdx.x >> 5;         // 0..7 ns slice
    const int c4 = blockIdx.x * 32 + g;      // global float4 channel group

    __shared__ float4 ssum[8][32];
    __shared__ float4 smax[8][32];
    __shared__ int    scnt[64];
    __shared__ float  scount;

    if (threadIdx.x < NS)
        scnt[threadIdx.x] = g_pcnt[b * NS + threadIdx.x];

    float4 sum = make_float4(0.f, 0.f, 0.f, 0.f);
    float4 mx  = make_float4(-FLT_MAX, -FLT_MAX, -FLT_MAX, -FLT_MAX);
    #pragma unroll
    for (int k = 0; k < 8; k++) {
        const int ns = sl * 8 + k;
        float4 s = reinterpret_cast<const float4*>(g_psum + (b * NS + ns) * CC)[c4];
        float4 m = reinterpret_cast<const float4*>(g_pmax + (b * NS + ns) * CC)[c4];
        sum.x += s.x; sum.y += s.y; sum.z += s.z; sum.w += s.w;
        mx.x = fmaxf(mx.x, m.x); mx.y = fmaxf(mx.y, m.y);
        mx.z = fmaxf(mx.z, m.z); mx.w = fmaxf(mx.w, m.w);
    }
    ssum[sl][g] = sum;
    smax[sl][g] = mx;
    __syncthreads();

    if (threadIdx.x == 0) {
        int c = 0;
        #pragma unroll
        for (int i = 0; i < NS; i++) c += scnt[i];
        scount = fmaxf((float)c, 1.0f);
    }
    __syncthreads();

    if (sl == 0) {
        #pragma unroll
        for (int k = 1; k < 8; k++) {
            float4 s = ssum[k][g];
            float4 m = smax[k][g];
            sum.x += s.x; sum.y += s.y; sum.z += s.z; sum.w += s.w;
            mx.x = fmaxf(mx.x, m.x); mx.y = fmaxf(mx.y, m.y);
            mx.z = fmaxf(mx.z, m.z); mx.w = fmaxf(mx.w, m.w);
        }
        const float inv = 1.0f / scount;
        sum.x *= inv; sum.y *= inv; sum.z *= inv; sum.w *= inv;
        reinterpret_cast<float4*>(g_mean + b * CC)[c4] = sum;
        reinterpret_cast<float4*>(g_max  + b * CC)[c4] = mx;
    }
}

// ---------------------------------------------------------------------------
// Kernel 3a: hsum[b,j] = relu(mean[b]·W0[j]) + relu(max[b]·W0[j])
// grid (HH/8 = 8, BB), 256 threads = 8 warps, one warp per hidden unit.
// ---------------------------------------------------------------------------
__global__ void k_mlp1(const float* __restrict__ W0) {   // [H, C]
    const int b = blockIdx.y;
    const int warp = threadIdx.x >> 5;
    const int lane = threadIdx.x & 31;
    const int j = blockIdx.x * 8 + warp;

    __shared__ float smean[CC];
    __shared__ float smax [CC];
    for (int i = threadIdx.x; i < CC; i += blockDim.x) {
        smean[i] = g_mean[b * CC + i];
        smax [i] = g_max [b * CC + i];
    }
    __syncthreads();

    const float* w = W0 + j * CC;
    float dm = 0.0f, dx = 0.0f;
    #pragma unroll 8
    for (int k = lane; k < CC; k += 32) {
        float wv = w[k];
        dm += wv * smean[k];
        dx += wv * smax[k];
    }
    #pragma unroll
    for (int off = 16; off > 0; off >>= 1) {
        dm += __shfl_xor_sync(0xFFFFFFFFu, dm, off);
        dx += __shfl_xor_sync(0xFFFFFFFFu, dx, off);
    }
    if (lane == 0)
        g_hsum[b * HH + j] = fmaxf(dm, 0.0f) + fmaxf(dx, 0.0f);
}

// ---------------------------------------------------------------------------
// Kernel 3b: a[b,c] = sigmoid(W1[c]·hsum[b]).  grid (CC/256 = 4, BB), 256 thr.
// ---------------------------------------------------------------------------
__global__ void k_mlp2(const float* __restrict__ W1) {   // [C, H]
    const int b = blockIdx.y;
    const int c = blockIdx.x * blockDim.x + threadIdx.x;

    __shared__ float sh[HH];
    if (threadIdx.x < HH) sh[threadIdx.x] = g_hsum[b * HH + threadIdx.x];
    __syncthreads();

    const float4* w1 = reinterpret_cast<const float4*>(W1 + c * HH);
    float acc = 0.0f;
    #pragma unroll
    for (int j = 0; j < HH / 4; j++) {
        float4 w = w1[j];
        acc += w.x * sh[j * 4 + 0] + w.y * sh[j * 4 + 1]
             + w.z * sh[j * 4 + 2] + w.w * sh[j * 4 + 3];
    }
    g_a[b * CC + c] = 1.0f / (1.0f + expf(-acc));
}

// ---------------------------------------------------------------------------
// Kernel 4: out[b,s,c] = x[b,s,c] * a[b,c]   (float4 streaming, .cs hints)
// grid ((S*C/4)/256, B)
// ---------------------------------------------------------------------------
__global__ void k_scale(const float* __restrict__ x,
                        float*       __restrict__ out) {
    const int b = blockIdx.y;
    const unsigned i = blockIdx.x * blockDim.x + threadIdx.x;  // float4 idx
    const unsigned c4 = i & (CC / 4 - 1);                       // 0..255

    const size_t gi = (size_t)b * (SS * CC / 4) + i;
    float4 v = __ldcs(reinterpret_cast<const float4*>(x) + gi);
    float4 a = reinterpret_cast<const float4*>(g_a + b * CC)[c4];
    v.x *= a.x; v.y *= a.y; v.z *= a.z; v.w *= a.w;
    __stcs(reinterpret_cast<float4*>(out) + gi, v);
}

// ---------------------------------------------------------------------------
extern "C" void kernel_launch(void* const* d_in, const int* in_sizes, int n_in,
                              void* d_out, int out_size) {
    const float* x    = (const float*)d_in[0];   // [B,S,C]
    const int*   mask = (const int*)  d_in[1];   // [B,S]
    const float* W0   = (const float*)d_in[2];   // [H,C]
    const float* W1   = (const float*)d_in[3];   // [C,H]
    float*       out  = (float*)d_out;           // [B,S,C]

    (void)in_sizes; (void)n_in; (void)out_size;

    {   dim3 grid(NS, BB);               k_partial <<<grid, 256>>>(x, mask); }
    {   dim3 grid(CC / 4 / 32, BB);      k_finalize<<<grid, 256>>>();        }
    {   dim3 grid(HH / 8, BB);           k_mlp1    <<<grid, 256>>>(W0);      }
    {   dim3 grid(CC / 256, BB);         k_mlp2    <<<grid, 256>>>(W1);      }
    {   dim3 grid((SS * CC / 4) / 256, BB); k_scale<<<grid, 256>>>(x, out);  }
}